// round 7
// baseline (speedup 1.0000x reference)
#include <cuda_runtime.h>
#include <math.h>

#define NQ 16
#define NS 65536
#define BATCH 256
#define SLIM (BATCH * NS)          /* 16,777,216 floats */
#define MLIM (BATCH * 3 * NQ * 4)  /* 49,152 floats */

// Intermediate state + gate matrices in __device__ statics (R6 exonerated these).
__device__ __align__(16) float g_state[SLIM];
__device__ __align__(16) float g_M[MLIM];

__device__ __forceinline__ float sigm(float x) { return 1.0f / (1.0f + expf(-x)); }

__global__ void dummy_kernel(float* outf, unsigned capF) {
    if (capF > 0) outf[0] = 0.f;
}

// ---------------------------------------------------------------------------
// MLP + gate-matrix precompute: h = tanh(relu(X@W1+b1)@W2+b2);
// M = [[cx*cy*cz, -sx*sy*sz],[sx*sy*cz, cx*cy*sz]], angles 0.5*rot[l,q,:]*h[b,q].
// ---------------------------------------------------------------------------
__global__ void mlp_kernel(const float* __restrict__ X,
                           const float* __restrict__ rot,
                           const float* __restrict__ W1,
                           const float* __restrict__ b1,
                           const float* __restrict__ W2,
                           const float* __restrict__ b2)
{
    int b = blockIdx.x * blockDim.x + threadIdx.x;
    if (b >= BATCH) return;
    const float* x = X + b * 100;

    float a1[64];
    for (int j = 0; j < 64; j++) {
        float s = b1[j];
        #pragma unroll 4
        for (int k = 0; k < 100; k++) s += x[k] * W1[k * 64 + j];
        a1[j] = s > 0.f ? s : 0.f;
    }
    float h[16];
    #pragma unroll
    for (int q = 0; q < 16; q++) {
        float s = b2[q];
        #pragma unroll 8
        for (int j = 0; j < 64; j++) s += a1[j] * W2[j * 16 + q];
        h[q] = tanhf(s);
    }
    for (int l = 0; l < 3; l++) {
        #pragma unroll
        for (int q = 0; q < 16; q++) {
            float hv = 0.5f * h[q];
            float ax = rot[(l * 16 + q) * 3 + 0] * hv;
            float ay = rot[(l * 16 + q) * 3 + 1] * hv;
            float az = rot[(l * 16 + q) * 3 + 2] * hv;
            float cx, sx, cy, sy, cz, sz;
            sincosf(ax, &sx, &cx);
            sincosf(ay, &sy, &cy);
            sincosf(az, &sz, &cz);
            float* m = &g_M[((b * 3 + l) * NQ + q) * 4];
            m[0] =  cx * cy * cz;
            m[1] = -sx * sy * sz;
            m[2] =  sx * sy * cz;
            m[3] =  cx * cy * sz;
        }
    }
}

// ---------------------------------------------------------------------------
// Pass A: slab of 2048 states (bits 0..10). 256 threads x 8 regs. 1D grid:
// blockIdx.x = b*32 + hi (hi = state bits 11..15); state bits 0..2 = reg,
// 3..10 = thread. GEN: layer-1 product state generated analytically.
// Then gates q0..10 (non-GEN) and CNOTs q=0..9. Writes g_state only.
// ---------------------------------------------------------------------------
template <int LAYER, bool GEN>
__global__ void passA_kernel(const float* __restrict__ ent)
{
    __shared__ float buf[8][256];
    const int hi = blockIdx.x & 31;
    const int b  = blockIdx.x >> 5;
    const int t  = threadIdx.x;
    const float* M = &g_M[(b * 3 + LAYER) * NQ * 4];
    const unsigned base = ((unsigned)b << 16) + ((unsigned)hi << 11) + ((unsigned)t << 3);

    float v[8];
    if (GEN) {
        float ph = 1.f;
        #pragma unroll
        for (int q = 11; q < 16; q++) ph *= M[q * 4 + (((hi >> (q - 11)) & 1) ? 2 : 0)];
        #pragma unroll
        for (int q = 3; q < 11; q++)  ph *= M[q * 4 + (((t >> (q - 3)) & 1) ? 2 : 0)];
        #pragma unroll
        for (int r = 0; r < 8; r++) {
            float pr = ph;
            pr *= M[0 + ((r & 1) ? 2 : 0)];
            pr *= M[4 + ((r & 2) ? 2 : 0)];
            pr *= M[8 + ((r & 4) ? 2 : 0)];
            v[r] = pr;
        }
    } else {
        float4 u0 = *(const float4*)&g_state[base];
        float4 u1 = *(const float4*)&g_state[base + 4];
        v[0] = u0.x; v[1] = u0.y; v[2] = u0.z; v[3] = u0.w;
        v[4] = u1.x; v[5] = u1.y; v[6] = u1.z; v[7] = u1.w;

        #pragma unroll
        for (int q = 0; q < 3; q++) {
            const float m00 = M[q*4], m01 = M[q*4+1], m10 = M[q*4+2], m11 = M[q*4+3];
            #pragma unroll
            for (int i = 0; i < 8; i++) if (!(i & (1 << q))) {
                const int j = i | (1 << q);
                float a = v[i], c = v[j];
                v[i] = m00 * a + m01 * c;
                v[j] = m10 * a + m11 * c;
            }
        }
        #pragma unroll
        for (int q = 3; q < 8; q++) {
            const float m00 = M[q*4], m01 = M[q*4+1], m10 = M[q*4+2], m11 = M[q*4+3];
            const int lb = 1 << (q - 3);
            const bool up = (t & lb) != 0;
            #pragma unroll
            for (int r = 0; r < 8; r++) {
                float pv = __shfl_xor_sync(0xffffffffu, v[r], lb);
                v[r] = up ? (m11 * v[r] + m10 * pv) : (m00 * v[r] + m01 * pv);
            }
        }
        #pragma unroll
        for (int q = 8; q < 11; q++) {
            const float m00 = M[q*4], m01 = M[q*4+1], m10 = M[q*4+2], m11 = M[q*4+3];
            const int tb = 1 << (q - 3);
            __syncthreads();
            #pragma unroll
            for (int r = 0; r < 8; r++) buf[r][t] = v[r];
            __syncthreads();
            const bool up = (t & tb) != 0;
            #pragma unroll
            for (int r = 0; r < 8; r++) {
                float pv = buf[r][(t ^ tb) & 255];
                v[r] = up ? (m11 * v[r] + m10 * pv) : (m00 * v[r] + m01 * pv);
            }
        }
    }

    // CNOTs q=0..9 (ctrl q, target q+1), p = sigmoid(ent[layer,q])
    #pragma unroll
    for (int q = 0; q < 2; q++) {
        const float p = sigm(ent[LAYER * 15 + q]), om = 1.f - p;
        const int cb = 1 << q, tb2 = 1 << (q + 1);
        #pragma unroll
        for (int i = 0; i < 8; i++) if ((i & cb) && !(i & tb2)) {
            const int j = i | tb2;
            float a = v[i], c = v[j];
            v[i] = om * a + p * c;
            v[j] = om * c + p * a;
        }
    }
    {
        const float p = sigm(ent[LAYER * 15 + 2]), om = 1.f - p;
        #pragma unroll
        for (int r = 0; r < 8; r++) {
            float pv = __shfl_xor_sync(0xffffffffu, v[r], 1);
            if (r & 4) v[r] = om * v[r] + p * pv;
        }
    }
    #pragma unroll
    for (int q = 3; q < 7; q++) {
        const float p = sigm(ent[LAYER * 15 + q]), om = 1.f - p;
        const bool c = (t & (1 << (q - 3))) != 0;
        #pragma unroll
        for (int r = 0; r < 8; r++) {
            float pv = __shfl_xor_sync(0xffffffffu, v[r], 1 << (q - 2));
            if (c) v[r] = om * v[r] + p * pv;
        }
    }
    #pragma unroll
    for (int q = 7; q < 10; q++) {
        const float p = sigm(ent[LAYER * 15 + q]), om = 1.f - p;
        const int tb = 1 << (q - 2);
        const bool c = (t & (1 << (q - 3))) != 0;
        __syncthreads();
        #pragma unroll
        for (int r = 0; r < 8; r++) buf[r][t] = v[r];
        __syncthreads();
        #pragma unroll
        for (int r = 0; r < 8; r++) {
            float pv = buf[r][(t ^ tb) & 255];
            if (c) v[r] = om * v[r] + p * pv;
        }
    }

    *(float4*)&g_state[base]     = make_float4(v[0], v[1], v[2], v[3]);
    *(float4*)&g_state[base + 4] = make_float4(v[4], v[5], v[6], v[7]);
}

// ---------------------------------------------------------------------------
// Pass B: each thread owns the 32 states spanning bits 11..15 for one fixed
// low index (bits 0..10). 1D grid: blockIdx.x = b*8 + lowblk.
// OUT: write final output per mode (0 = flat real floats, 1 = interleaved
// (re,0) pairs), strictly guarded by capF (floats).
// ---------------------------------------------------------------------------
template <int LAYER, bool GATES, bool OUT>
__global__ void passB_kernel(const float* __restrict__ ent,
                             float* __restrict__ outf, unsigned capF, int mode)
{
    const int lowblk = blockIdx.x & 7;
    const int b = blockIdx.x >> 3;
    const int t = threadIdx.x;
    const int low = (lowblk << 8) | t;
    const float* M = &g_M[(b * 3 + LAYER) * NQ * 4];
    const unsigned base = ((unsigned)b << 16) + (unsigned)low;

    float w[32];
    #pragma unroll
    for (int k = 0; k < 32; k++) w[k] = g_state[base + ((unsigned)k << 11)];

    if (GATES) {
        #pragma unroll
        for (int q = 11; q < 16; q++) {
            const float m00 = M[q*4], m01 = M[q*4+1], m10 = M[q*4+2], m11 = M[q*4+3];
            const int kb = 1 << (q - 11);
            #pragma unroll
            for (int i = 0; i < 32; i++) if (!(i & kb)) {
                const int j = i | kb;
                float a = w[i], c = w[j];
                w[i] = m00 * a + m01 * c;
                w[j] = m10 * a + m11 * c;
            }
        }
    }
    // CNOT 10: ctrl = bit 10 of low, target = k bit 0
    {
        const float p = sigm(ent[LAYER * 15 + 10]), om = 1.f - p;
        if (low & 1024) {
            #pragma unroll
            for (int i = 0; i < 32; i += 2) {
                float a = w[i], c = w[i + 1];
                w[i]     = om * a + p * c;
                w[i + 1] = om * c + p * a;
            }
        }
    }
    // CNOTs 11..14
    #pragma unroll
    for (int q = 11; q < 15; q++) {
        const float p = sigm(ent[LAYER * 15 + q]), om = 1.f - p;
        const int cb = 1 << (q - 11), tb = 1 << (q - 10);
        #pragma unroll
        for (int i = 0; i < 32; i++) if ((i & cb) && !(i & tb)) {
            const int j = i | tb;
            float a = w[i], c = w[j];
            w[i] = om * a + p * c;
            w[j] = om * c + p * a;
        }
    }

    if (OUT) {
        if (mode == 1) {
            // complex64 layout: (re, 0) pairs
            #pragma unroll
            for (int k = 0; k < 32; k++) {
                unsigned idx = base + ((unsigned)k << 11);
                unsigned p2 = 2u * idx;
                if (p2 + 1u < capF) {
                    outf[p2]      = w[k];
                    outf[p2 + 1u] = 0.f;
                }
            }
        } else {
            // flat float layout: real values only
            #pragma unroll
            for (int k = 0; k < 32; k++) {
                unsigned idx = base + ((unsigned)k << 11);
                if (idx < capF) outf[idx] = w[k];
            }
        }
    } else {
        #pragma unroll
        for (int k = 0; k < 32; k++) g_state[base + ((unsigned)k << 11)] = w[k];
    }
}

// ---------------------------------------------------------------------------
extern "C" void kernel_launch(void* const* d_in, const int* in_sizes, int n_in,
                              void* d_out, int out_size)
{
    static const long long want[7] = {25600, 144, 45, 6400, 64, 1024, 16};
    const float* ptr[7] = {0, 0, 0, 0, 0, 0, 0};

    bool bound = false;
    for (int scale = 1; scale <= 4 && !bound; scale *= 4) {
        const float* tmp[7] = {0, 0, 0, 0, 0, 0, 0};
        int m = 0;
        for (int i = 0; i < n_in; i++) {
            long long s = (long long)in_sizes[i];
            for (int j = 0; j < 7; j++) {
                if (!tmp[j] && s == want[j] * scale) { tmp[j] = (const float*)d_in[i]; m++; break; }
            }
        }
        if (m == 7) { for (int j = 0; j < 7; j++) ptr[j] = tmp[j]; bound = true; }
    }
    if (!bound && n_in >= 7) {
        for (int j = 0; j < 7; j++) ptr[j] = (const float*)d_in[j];
        bound = true;
    }

    float* outf = (float*)d_out;

    // Pessimistic output capacity (floats) + layout mode.
    // out_size >= 33,554,432 : buffer holds >= 32M floats under every sane
    //   convention (float count, complex-element count*8B, or raw bytes) ->
    //   interleaved complex layout, cap 33,554,432 floats.
    // out_size == 16,777,216 : ambiguous (complex count -> 134MB buffer, OR
    //   float-sized 64MB buffer). Pessimistic: cap 16,777,216 floats (64MB,
    //   safe under BOTH) and write flat real values.
    long long os = (long long)out_size;
    unsigned capF;
    int mode;
    if (os >= 33554432LL)      { mode = 1; capF = 33554432u; }
    else if (os == 16777216LL) { mode = 0; capF = 16777216u; }
    else {
        mode = 0;
        long long c = os > 0 ? os : 0;
        if (c > 33554432LL) c = 33554432LL;
        capF = (unsigned)c;
    }

    if (!bound || !outf) {
        dummy_kernel<<<1, 32>>>(outf, capF);
        return;
    }

    mlp_kernel<<<2, 128>>>(ptr[0], ptr[1], ptr[3], ptr[4], ptr[5], ptr[6]);

    const float* ent = ptr[2];
    const int GA = 32 * BATCH;  // 8192 blocks
    const int GB = 8 * BATCH;   // 2048 blocks
    passA_kernel<0, true ><<<GA, 256>>>(ent);
    passB_kernel<0, false, false><<<GB, 256>>>(ent, outf, capF, mode);
    passA_kernel<1, false><<<GA, 256>>>(ent);
    passB_kernel<1, true , false><<<GB, 256>>>(ent, outf, capF, mode);
    passA_kernel<2, false><<<GA, 256>>>(ent);
    passB_kernel<2, true , true ><<<GB, 256>>>(ent, outf, capF, mode);
}

// round 8
// speedup vs baseline: 2.7020x; 2.7020x over previous
#include <cuda_runtime.h>
#include <math.h>

#define NQ 16
#define NS 65536
#define BATCH 256
#define SLIM (BATCH * NS)          /* 16,777,216 floats */
#define MLIM (BATCH * 3 * NQ * 4)  /* 49,152 floats */

__device__ __align__(16) float g_state[SLIM];
__device__ __align__(16) float g_M[MLIM];
__device__ float g_P[48];   // sigmoid(entangling_params), 45 used

__device__ __forceinline__ float sigm(float x) { return 1.0f / (1.0f + expf(-x)); }

// Swizzle for the in-block transposes: conflict-free for all phase patterns.
__device__ __forceinline__ unsigned sw(unsigned s) {
    return s ^ (((s >> 5) & 7u) | (((s >> 6) & 3u) << 3));
}

// In-register 2x2 gate on register-bit kb.
__device__ __forceinline__ void gate_reg(float v[8], int kb,
                                         float m00, float m01, float m10, float m11) {
    #pragma unroll
    for (int i = 0; i < 8; i++) if (!(i & kb)) {
        const int j = i | kb;
        float a = v[i], c = v[j];
        v[i] = m00 * a + m01 * c;
        v[j] = m10 * a + m11 * c;
    }
}
// Noisy CNOT, ctrl and target both register bits.
__device__ __forceinline__ void cnot_reg(float v[8], int cb, int tb, float p) {
    const float om = 1.f - p;
    #pragma unroll
    for (int i = 0; i < 8; i++) if ((i & cb) && !(i & tb)) {
        const int j = i | tb;
        float a = v[i], c = v[j];
        v[i] = om * a + p * c;
        v[j] = om * c + p * a;
    }
}
// Noisy CNOT, ctrl outside registers (uniform per thread), target register bit.
__device__ __forceinline__ void cnot_reg_ext(float v[8], int tb, bool ctrl, float p) {
    const float pp = ctrl ? p : 0.f;
    const float oo = ctrl ? 1.f - p : 1.f;
    #pragma unroll
    for (int i = 0; i < 8; i++) if (!(i & tb)) {
        const int j = i | tb;
        float a = v[i], c = v[j];
        v[i] = oo * a + pp * c;
        v[j] = oo * c + pp * a;
    }
}

__global__ void dummy_kernel(float* outf, unsigned capF) {
    if (capF > 0) outf[0] = 0.f;
}

// ---------------------------------------------------------------------------
// MLP + gate matrices + sigmoid table. One block per batch element.
// ---------------------------------------------------------------------------
__global__ void mlp_kernel(const float* __restrict__ X,
                           const float* __restrict__ rot,
                           const float* __restrict__ ent,
                           const float* __restrict__ W1,
                           const float* __restrict__ b1,
                           const float* __restrict__ W2,
                           const float* __restrict__ b2)
{
    __shared__ float sx[100];
    __shared__ float sa[64];
    __shared__ float sh[16];
    const int b = blockIdx.x;
    const int j = threadIdx.x;  // 64 threads

    if (b == 0 && j < 45) g_P[j] = sigm(ent[j]);

    for (int k = j; k < 100; k += 64) sx[k] = X[b * 100 + k];
    __syncthreads();
    {
        float s = b1[j];
        #pragma unroll 4
        for (int k = 0; k < 100; k++) s = fmaf(sx[k], W1[k * 64 + j], s);
        sa[j] = s > 0.f ? s : 0.f;
    }
    __syncthreads();
    if (j < 16) {
        float s = b2[j];
        #pragma unroll 8
        for (int k = 0; k < 64; k++) s = fmaf(sa[k], W2[k * 16 + j], s);
        sh[j] = tanhf(s);
    }
    __syncthreads();
    if (j < 48) {
        const int l = j >> 4, q = j & 15;
        float hv = 0.5f * sh[q];
        float ax = rot[(l * 16 + q) * 3 + 0] * hv;
        float ay = rot[(l * 16 + q) * 3 + 1] * hv;
        float az = rot[(l * 16 + q) * 3 + 2] * hv;
        float cx, sx2, cy, sy, cz, sz;
        sincosf(ax, &sx2, &cx);
        sincosf(ay, &sy,  &cy);
        sincosf(az, &sz,  &cz);
        float* m = &g_M[((b * 3 + l) * NQ + q) * 4];
        m[0] =  cx * cy * cz;
        m[1] = -sx2 * sy * sz;
        m[2] =  sx2 * sy * cz;
        m[3] =  cx * cy * sz;
    }
}

// ---------------------------------------------------------------------------
// Pass A: slab of 2048 states (bits 0..10), 256 threads x 8 regs.
// Register phases (regs = state bits): m0 = 0..2, m1 = 3..5, m2 = 6..8,
// m3 = 8..10, connected by swizzled smem transposes (double buffered).
// GEN: layer-0 product state generated analytically (all 16 gates folded).
// Phase ops:
//   m0: [load+G0..G2] C0 C1
//   m1: [G3..G5] C2(ext ctrl=bit2) C3 C4
//   m2: [G6..G8] C5(ext ctrl=bit5) C6 C7
//   m3: [G9 G10] C8 C9, store (coalesced: s = r<<8 | t)
// ---------------------------------------------------------------------------
template <int LAYER, bool GEN>
__global__ void __launch_bounds__(256) passA_kernel()
{
    __shared__ float sm[2][2048];
    const int hi = blockIdx.x & 31;
    const int b  = blockIdx.x >> 5;
    const int t  = threadIdx.x;
    const float* M = &g_M[(b * 3 + LAYER) * 64];
    const float* P = &g_P[LAYER * 15];
    const unsigned base = ((unsigned)b << 16) + ((unsigned)hi << 11);

    float v[8];
    // ---- m0: regs = bits 0..2, thread = bits 3..10 ----
    if (GEN) {
        float ph = 1.f;
        #pragma unroll
        for (int q = 11; q < 16; q++) ph *= M[q * 4 + (((hi >> (q - 11)) & 1) ? 2 : 0)];
        #pragma unroll
        for (int q = 3; q < 11; q++)  ph *= M[q * 4 + (((t >> (q - 3)) & 1) ? 2 : 0)];
        #pragma unroll
        for (int r = 0; r < 8; r++) {
            float pr = ph;
            pr *= M[0 + ((r & 1) ? 2 : 0)];
            pr *= M[4 + ((r & 2) ? 2 : 0)];
            pr *= M[8 + ((r & 4) ? 2 : 0)];
            v[r] = pr;
        }
    } else {
        const float4 u0 = *(const float4*)&g_state[base + ((unsigned)t << 3)];
        const float4 u1 = *(const float4*)&g_state[base + ((unsigned)t << 3) + 4];
        v[0] = u0.x; v[1] = u0.y; v[2] = u0.z; v[3] = u0.w;
        v[4] = u1.x; v[5] = u1.y; v[6] = u1.z; v[7] = u1.w;
        gate_reg(v, 1, M[0], M[1], M[2],  M[3]);   // G0
        gate_reg(v, 2, M[4], M[5], M[6],  M[7]);   // G1
        gate_reg(v, 4, M[8], M[9], M[10], M[11]);  // G2
    }
    cnot_reg(v, 1, 2, P[0]);   // C0 (bits 0->1)
    cnot_reg(v, 2, 4, P[1]);   // C1 (bits 1->2)

    // ---- T1 -> m1: regs = bits 3..5, thread low3 = bits 0..2, high5 = bits 6..10
    #pragma unroll
    for (int r = 0; r < 8; r++) { unsigned s = ((unsigned)t << 3) | r; sm[0][sw(s)] = v[r]; }
    __syncthreads();
    #pragma unroll
    for (int r = 0; r < 8; r++) {
        unsigned s = (((unsigned)t >> 3) << 6) | ((unsigned)r << 3) | (t & 7);
        v[r] = sm[0][sw(s)];
    }
    if (!GEN) {
        gate_reg(v, 1, M[12], M[13], M[14], M[15]);  // G3
        gate_reg(v, 2, M[16], M[17], M[18], M[19]);  // G4
        gate_reg(v, 4, M[20], M[21], M[22], M[23]);  // G5
    }
    cnot_reg_ext(v, 1, (t & 4) != 0, P[2]);  // C2 (ctrl bit2 = t bit2, tgt bit3)
    cnot_reg(v, 1, 2, P[3]);                 // C3 (3->4)
    cnot_reg(v, 2, 4, P[4]);                 // C4 (4->5)

    // ---- T2 -> m2: regs = bits 6..8, thread low6 = bits 0..5, high2 = bits 9..10
    #pragma unroll
    for (int r = 0; r < 8; r++) {
        unsigned s = (((unsigned)t >> 3) << 6) | ((unsigned)r << 3) | (t & 7);
        sm[1][sw(s)] = v[r];
    }
    __syncthreads();
    #pragma unroll
    for (int r = 0; r < 8; r++) {
        unsigned s = (((unsigned)t >> 6) << 9) | ((unsigned)r << 6) | (t & 63);
        v[r] = sm[1][sw(s)];
    }
    if (!GEN) {
        gate_reg(v, 1, M[24], M[25], M[26], M[27]);  // G6
        gate_reg(v, 2, M[28], M[29], M[30], M[31]);  // G7
        gate_reg(v, 4, M[32], M[33], M[34], M[35]);  // G8
    }
    cnot_reg_ext(v, 1, (t & 32) != 0, P[5]);  // C5 (ctrl bit5 = t bit5, tgt bit6)
    cnot_reg(v, 1, 2, P[6]);                  // C6 (6->7)
    cnot_reg(v, 2, 4, P[7]);                  // C7 (7->8)

    // ---- T3 -> m3: regs = bits 8..10, thread = bits 0..7
    #pragma unroll
    for (int r = 0; r < 8; r++) {
        unsigned s = (((unsigned)t >> 6) << 9) | ((unsigned)r << 6) | (t & 63);
        sm[0][sw(s)] = v[r];
    }
    __syncthreads();
    #pragma unroll
    for (int r = 0; r < 8; r++) {
        unsigned s = ((unsigned)r << 8) | (unsigned)t;
        v[r] = sm[0][sw(s)];
    }
    if (!GEN) {
        gate_reg(v, 2, M[36], M[37], M[38], M[39]);  // G9  (bit 9 = reg bit 1)
        gate_reg(v, 4, M[40], M[41], M[42], M[43]);  // G10 (bit 10 = reg bit 2)
    }
    cnot_reg(v, 1, 2, P[8]);  // C8 (8->9)
    cnot_reg(v, 2, 4, P[9]);  // C9 (9->10)

    #pragma unroll
    for (int r = 0; r < 8; r++) g_state[base + ((unsigned)r << 8) + (unsigned)t] = v[r];
}

// ---------------------------------------------------------------------------
// Pass B: each thread owns the 32 states spanning bits 11..15 for one fixed
// low index (bits 0..10). Gates 11..15 (GATES), CNOT 10, CNOTs 11..14.
// OUT: final output write per mode (0 = flat floats, 1 = (re,0) pairs).
// ---------------------------------------------------------------------------
template <int LAYER, bool GATES, bool OUT>
__global__ void __launch_bounds__(256) passB_kernel(float* __restrict__ outf,
                                                    unsigned capF, int mode)
{
    const int lowblk = blockIdx.x & 7;
    const int b = blockIdx.x >> 3;
    const int t = threadIdx.x;
    const int low = (lowblk << 8) | t;
    const float* M = &g_M[(b * 3 + LAYER) * 64];
    const float* P = &g_P[LAYER * 15];
    const unsigned base = ((unsigned)b << 16) + (unsigned)low;

    float w[32];
    #pragma unroll
    for (int k = 0; k < 32; k++) w[k] = g_state[base + ((unsigned)k << 11)];

    if (GATES) {
        #pragma unroll
        for (int q = 11; q < 16; q++) {
            const float m00 = M[q*4], m01 = M[q*4+1], m10 = M[q*4+2], m11 = M[q*4+3];
            const int kb = 1 << (q - 11);
            #pragma unroll
            for (int i = 0; i < 32; i++) if (!(i & kb)) {
                const int j = i | kb;
                float a = w[i], c = w[j];
                w[i] = m00 * a + m01 * c;
                w[j] = m10 * a + m11 * c;
            }
        }
    }
    // C10: ctrl = bit 10 of low, target = k bit 0
    {
        const float p = P[10], om = 1.f - p;
        if (low & 1024) {
            #pragma unroll
            for (int i = 0; i < 32; i += 2) {
                float a = w[i], c = w[i + 1];
                w[i]     = om * a + p * c;
                w[i + 1] = om * c + p * a;
            }
        }
    }
    // C11..C14
    #pragma unroll
    for (int q = 11; q < 15; q++) {
        const float p = P[q], om = 1.f - p;
        const int cb = 1 << (q - 11), tb = 1 << (q - 10);
        #pragma unroll
        for (int i = 0; i < 32; i++) if ((i & cb) && !(i & tb)) {
            const int j = i | tb;
            float a = w[i], c = w[j];
            w[i] = om * a + p * c;
            w[j] = om * c + p * a;
        }
    }

    if (OUT) {
        if (mode == 1) {
            #pragma unroll
            for (int k = 0; k < 32; k++) {
                unsigned idx = base + ((unsigned)k << 11);
                unsigned p2 = 2u * idx;
                if (p2 + 1u < capF) *(float2*)&outf[p2] = make_float2(w[k], 0.f);
            }
        } else {
            #pragma unroll
            for (int k = 0; k < 32; k++) {
                unsigned idx = base + ((unsigned)k << 11);
                if (idx < capF) outf[idx] = w[k];
            }
        }
    } else {
        #pragma unroll
        for (int k = 0; k < 32; k++) g_state[base + ((unsigned)k << 11)] = w[k];
    }
}

// ---------------------------------------------------------------------------
extern "C" void kernel_launch(void* const* d_in, const int* in_sizes, int n_in,
                              void* d_out, int out_size)
{
    static const long long want[7] = {25600, 144, 45, 6400, 64, 1024, 16};
    const float* ptr[7] = {0, 0, 0, 0, 0, 0, 0};

    bool bound = false;
    for (int scale = 1; scale <= 4 && !bound; scale *= 4) {
        const float* tmp[7] = {0, 0, 0, 0, 0, 0, 0};
        int m = 0;
        for (int i = 0; i < n_in; i++) {
            long long s = (long long)in_sizes[i];
            for (int j = 0; j < 7; j++) {
                if (!tmp[j] && s == want[j] * scale) { tmp[j] = (const float*)d_in[i]; m++; break; }
            }
        }
        if (m == 7) { for (int j = 0; j < 7; j++) ptr[j] = tmp[j]; bound = true; }
    }
    if (!bound && n_in >= 7) {
        for (int j = 0; j < 7; j++) ptr[j] = (const float*)d_in[j];
        bound = true;
    }

    float* outf = (float*)d_out;

    // Output capacity + layout mode — identical to the passing R7 logic.
    long long os = (long long)out_size;
    unsigned capF;
    int mode;
    if (os >= 33554432LL)      { mode = 1; capF = 33554432u; }
    else if (os == 16777216LL) { mode = 0; capF = 16777216u; }
    else {
        mode = 0;
        long long c = os > 0 ? os : 0;
        if (c > 33554432LL) c = 33554432LL;
        capF = (unsigned)c;
    }

    if (!bound || !outf) {
        dummy_kernel<<<1, 32>>>(outf, capF);
        return;
    }

    mlp_kernel<<<BATCH, 64>>>(ptr[0], ptr[1], ptr[2], ptr[3], ptr[4], ptr[5], ptr[6]);

    const int GA = 32 * BATCH;  // 8192 blocks
    const int GB = 8 * BATCH;   // 2048 blocks
    passA_kernel<0, true ><<<GA, 256>>>();
    passB_kernel<0, false, false><<<GB, 256>>>(outf, capF, mode);
    passA_kernel<1, false><<<GA, 256>>>();
    passB_kernel<1, true , false><<<GB, 256>>>(outf, capF, mode);
    passA_kernel<2, false><<<GA, 256>>>();
    passB_kernel<2, true , true ><<<GB, 256>>>(outf, capF, mode);
}

// round 9
// speedup vs baseline: 3.0828x; 1.1409x over previous
#include <cuda_runtime.h>
#include <math.h>

#define NQ 16
#define NS 65536
#define BATCH 256
#define SLIM (BATCH * NS)          /* 16,777,216 floats */
#define MLIM (BATCH * 3 * NQ * 4)  /* 49,152 floats */

__device__ __align__(16) float g_state[SLIM];
__device__ __align__(16) float g_M[MLIM];
__device__ float g_P[48];   // sigmoid(entangling_params), 45 used

__device__ __forceinline__ float sigm(float x) { return 1.0f / (1.0f + expf(-x)); }

// Padded smem addressing (proven conflict-free for each access pattern):
//   addrA(s) = s + 4*(s>>4) + 16*(s>>8)   (T1: float4 write / stride-16 read)
//   addrB(s) = s + 16*(s>>8)              (T2: stride-16 write / stride-256 read)
#define ADDRA(s) ((s) + 4u * ((s) >> 4) + 16u * ((s) >> 8))
#define ADDRB(s) ((s) + 16u * ((s) >> 8))
#define SMEM_FLOATS 5376  /* >= max addrA = 5355 */

// In-register 2x2 gate on register-bit kb (N-element tile).
template <int N>
__device__ __forceinline__ void gate_reg(float* v, int kb,
                                         float m00, float m01, float m10, float m11) {
    #pragma unroll
    for (int i = 0; i < N; i++) if (!(i & kb)) {
        const int j = i | kb;
        float a = v[i], c = v[j];
        v[i] = m00 * a + m01 * c;
        v[j] = m10 * a + m11 * c;
    }
}
// Noisy CNOT, ctrl and target both register bits.
template <int N>
__device__ __forceinline__ void cnot_reg(float* v, int cb, int tb, float p) {
    const float om = 1.f - p;
    #pragma unroll
    for (int i = 0; i < N; i++) if ((i & cb) && !(i & tb)) {
        const int j = i | tb;
        float a = v[i], c = v[j];
        v[i] = om * a + p * c;
        v[j] = om * c + p * a;
    }
}
// Noisy CNOT, ctrl outside registers (uniform per thread), target register bit.
template <int N>
__device__ __forceinline__ void cnot_reg_ext(float* v, int tb, bool ctrl, float p) {
    const float pp = ctrl ? p : 0.f;
    const float oo = ctrl ? 1.f - p : 1.f;
    #pragma unroll
    for (int i = 0; i < N; i++) if (!(i & tb)) {
        const int j = i | tb;
        float a = v[i], c = v[j];
        v[i] = oo * a + pp * c;
        v[j] = oo * c + pp * a;
    }
}

__global__ void dummy_kernel(float* outf, unsigned capF) {
    if (capF > 0) outf[0] = 0.f;
}

// ---------------------------------------------------------------------------
// MLP + gate matrices + sigmoid table. One block per batch element.
// ---------------------------------------------------------------------------
__global__ void mlp_kernel(const float* __restrict__ X,
                           const float* __restrict__ rot,
                           const float* __restrict__ ent,
                           const float* __restrict__ W1,
                           const float* __restrict__ b1,
                           const float* __restrict__ W2,
                           const float* __restrict__ b2)
{
    __shared__ float sx[100];
    __shared__ float sa[64];
    __shared__ float sh[16];
    const int b = blockIdx.x;
    const int j = threadIdx.x;  // 64 threads

    if (b == 0 && j < 45) g_P[j] = sigm(ent[j]);

    for (int k = j; k < 100; k += 64) sx[k] = X[b * 100 + k];
    __syncthreads();
    {
        float s = b1[j];
        #pragma unroll 4
        for (int k = 0; k < 100; k++) s = fmaf(sx[k], W1[k * 64 + j], s);
        sa[j] = s > 0.f ? s : 0.f;
    }
    __syncthreads();
    if (j < 16) {
        float s = b2[j];
        #pragma unroll 8
        for (int k = 0; k < 64; k++) s = fmaf(sa[k], W2[k * 16 + j], s);
        sh[j] = tanhf(s);
    }
    __syncthreads();
    if (j < 48) {
        const int l = j >> 4, q = j & 15;
        float hv = 0.5f * sh[q];
        float ax = rot[(l * 16 + q) * 3 + 0] * hv;
        float ay = rot[(l * 16 + q) * 3 + 1] * hv;
        float az = rot[(l * 16 + q) * 3 + 2] * hv;
        float cx, sx2, cy, sy, cz, sz;
        sincosf(ax, &sx2, &cx);
        sincosf(ay, &sy,  &cy);
        sincosf(az, &sz,  &cz);
        float* m = &g_M[((b * 3 + l) * NQ + q) * 4];
        m[0] =  cx * cy * cz;
        m[1] = -sx2 * sy * sz;
        m[2] =  sx2 * sy * cz;
        m[3] =  cx * cy * sz;
    }
}

// ---------------------------------------------------------------------------
// Pass A: slab of 4096 states (bits 0..11), 256 threads x 16 regs.
// Register phases: m0 = bits 0..3 (thread = bits 4..11),
//                  m1 = bits 4..7 (thread low4 = bits 0..3, high4 = bits 8..11),
//                  m2 = bits 8..11 (thread = bits 0..7),
// connected by 2 padded-smem transposes (single buffer, 3 barriers).
// GEN: layer-0 product state generated analytically in m0 layout.
// Ops: m0: [load+G0..3] C0 C1 C2 | m1: [G4..7] C3ext C4 C5 C6
//      m2: [G8..11] C7ext C8 C9 C10, coalesced store.
// ---------------------------------------------------------------------------
template <int LAYER, bool GEN>
__global__ void __launch_bounds__(256) passA_kernel()
{
    __shared__ float sm[SMEM_FLOATS];
    const int hi = blockIdx.x & 15;   // state bits 12..15
    const int b  = blockIdx.x >> 4;
    const unsigned t = threadIdx.x;   // 0..255
    const float* M = &g_M[(b * 3 + LAYER) * 64];
    const float* P = &g_P[LAYER * 15];
    const unsigned base = ((unsigned)b << 16) + ((unsigned)hi << 12);

    float v[16];
    // ---- m0: regs = bits 0..3, thread = bits 4..11 ----
    if (GEN) {
        float ph = 1.f;
        #pragma unroll
        for (int q = 12; q < 16; q++) ph *= M[q * 4 + (((hi >> (q - 12)) & 1) ? 2 : 0)];
        #pragma unroll
        for (int q = 4; q < 12; q++)  ph *= M[q * 4 + (((t >> (q - 4)) & 1) ? 2 : 0)];
        #pragma unroll
        for (int r = 0; r < 16; r++) {
            float pr = ph;
            pr *= M[0  + ((r & 1) ? 2 : 0)];
            pr *= M[4  + ((r & 2) ? 2 : 0)];
            pr *= M[8  + ((r & 4) ? 2 : 0)];
            pr *= M[12 + ((r & 8) ? 2 : 0)];
            v[r] = pr;
        }
    } else {
        #pragma unroll
        for (int k = 0; k < 4; k++) {
            const float4 u = *(const float4*)&g_state[base + (t << 4) + 4u * k];
            v[4*k+0] = u.x; v[4*k+1] = u.y; v[4*k+2] = u.z; v[4*k+3] = u.w;
        }
        gate_reg<16>(v, 1, M[0],  M[1],  M[2],  M[3]);   // G0
        gate_reg<16>(v, 2, M[4],  M[5],  M[6],  M[7]);   // G1
        gate_reg<16>(v, 4, M[8],  M[9],  M[10], M[11]);  // G2
        gate_reg<16>(v, 8, M[12], M[13], M[14], M[15]);  // G3
    }
    cnot_reg<16>(v, 1, 2, P[0]);   // C0 (0->1)
    cnot_reg<16>(v, 2, 4, P[1]);   // C1 (1->2)
    cnot_reg<16>(v, 4, 8, P[2]);   // C2 (2->3)

    // ---- T1 (bufA addressing): float4 writes, stride-16 reads ----
    {
        float4* s4 = (float4*)sm;
        const unsigned w4 = t * 5u + 4u * (t >> 4);  // ADDRA(t*16+4k)/4 - k offset below
        #pragma unroll
        for (int k = 0; k < 4; k++)
            s4[w4 + k] = make_float4(v[4*k], v[4*k+1], v[4*k+2], v[4*k+3]);
    }
    __syncthreads();
    {
        const unsigned rbase = (t & 15u) + 336u * (t >> 4);  // ADDRA of ((t>>4)<<8 | r<<4 | (t&15))
        #pragma unroll
        for (int r = 0; r < 16; r++) v[r] = sm[rbase + 20u * r];
    }
    // ---- m1: regs = bits 4..7 ----
    if (!GEN) {
        gate_reg<16>(v, 1, M[16], M[17], M[18], M[19]);  // G4
        gate_reg<16>(v, 2, M[20], M[21], M[22], M[23]);  // G5
        gate_reg<16>(v, 4, M[24], M[25], M[26], M[27]);  // G6
        gate_reg<16>(v, 8, M[28], M[29], M[30], M[31]);  // G7
    }
    cnot_reg_ext<16>(v, 1, (t & 8u) != 0, P[3]);  // C3 (ctrl bit3 = t bit3, tgt bit4)
    cnot_reg<16>(v, 1, 2, P[4]);                  // C4 (4->5)
    cnot_reg<16>(v, 2, 4, P[5]);                  // C5 (5->6)
    cnot_reg<16>(v, 4, 8, P[6]);                  // C6 (6->7)

    __syncthreads();  // WAR: everyone done reading bufA before bufB overwrite

    // ---- T2 (bufB addressing): stride-16 writes, stride-272 reads ----
    {
        const unsigned wbase = (t & 15u) + 272u * (t >> 4);  // ADDRB of ((t>>4)<<8 | r<<4 | (t&15))
        #pragma unroll
        for (int r = 0; r < 16; r++) sm[wbase + 16u * r] = v[r];
    }
    __syncthreads();
    {
        #pragma unroll
        for (int r = 0; r < 16; r++) v[r] = sm[272u * r + t];  // ADDRB of (r<<8 | t)
    }
    // ---- m2: regs = bits 8..11, thread = bits 0..7 ----
    if (!GEN) {
        gate_reg<16>(v, 1, M[32], M[33], M[34], M[35]);  // G8
        gate_reg<16>(v, 2, M[36], M[37], M[38], M[39]);  // G9
        gate_reg<16>(v, 4, M[40], M[41], M[42], M[43]);  // G10
        gate_reg<16>(v, 8, M[44], M[45], M[46], M[47]);  // G11
    }
    cnot_reg_ext<16>(v, 1, (t & 128u) != 0, P[7]);  // C7 (ctrl bit7 = t bit7, tgt bit8)
    cnot_reg<16>(v, 1, 2, P[8]);                    // C8 (8->9)
    cnot_reg<16>(v, 2, 4, P[9]);                    // C9 (9->10)
    cnot_reg<16>(v, 4, 8, P[10]);                   // C10 (10->11)

    #pragma unroll
    for (int r = 0; r < 16; r++) g_state[base + ((unsigned)r << 8) + t] = v[r];
}

// ---------------------------------------------------------------------------
// Pass B: each thread owns the 16 states spanning bits 12..15 for one fixed
// low index (bits 0..11). Gates G12..15 (GATES), C11 (uniform ctrl bit 11),
// C12..C14. OUT: final output write per mode (0 = flat floats, 1 = (re,0)).
// ---------------------------------------------------------------------------
template <int LAYER, bool GATES, bool OUT>
__global__ void __launch_bounds__(256) passB_kernel(float* __restrict__ outf,
                                                    unsigned capF, int mode)
{
    const int lowblk = blockIdx.x & 15;  // low bits 8..11
    const int b = blockIdx.x >> 4;
    const unsigned t = threadIdx.x;
    const unsigned low = ((unsigned)lowblk << 8) | t;
    const float* M = &g_M[(b * 3 + LAYER) * 64];
    const float* P = &g_P[LAYER * 15];
    const unsigned base = ((unsigned)b << 16) + low;

    float w[16];
    #pragma unroll
    for (int k = 0; k < 16; k++) w[k] = g_state[base + ((unsigned)k << 12)];

    if (GATES) {
        gate_reg<16>(w, 1, M[48], M[49], M[50], M[51]);  // G12
        gate_reg<16>(w, 2, M[52], M[53], M[54], M[55]);  // G13
        gate_reg<16>(w, 4, M[56], M[57], M[58], M[59]);  // G14
        gate_reg<16>(w, 8, M[60], M[61], M[62], M[63]);  // G15
    }
    cnot_reg_ext<16>(w, 1, (low & 2048u) != 0, P[11]);  // C11 (ctrl bit11, tgt bit12)
    cnot_reg<16>(w, 1, 2, P[12]);                       // C12 (12->13)
    cnot_reg<16>(w, 2, 4, P[13]);                       // C13 (13->14)
    cnot_reg<16>(w, 4, 8, P[14]);                       // C14 (14->15)

    if (OUT) {
        if (mode == 1) {
            #pragma unroll
            for (int k = 0; k < 16; k++) {
                unsigned idx = base + ((unsigned)k << 12);
                unsigned p2 = 2u * idx;
                if (p2 + 1u < capF) *(float2*)&outf[p2] = make_float2(w[k], 0.f);
            }
        } else {
            #pragma unroll
            for (int k = 0; k < 16; k++) {
                unsigned idx = base + ((unsigned)k << 12);
                if (idx < capF) outf[idx] = w[k];
            }
        }
    } else {
        #pragma unroll
        for (int k = 0; k < 16; k++) g_state[base + ((unsigned)k << 12)] = w[k];
    }
}

// ---------------------------------------------------------------------------
extern "C" void kernel_launch(void* const* d_in, const int* in_sizes, int n_in,
                              void* d_out, int out_size)
{
    static const long long want[7] = {25600, 144, 45, 6400, 64, 1024, 16};
    const float* ptr[7] = {0, 0, 0, 0, 0, 0, 0};

    bool bound = false;
    for (int scale = 1; scale <= 4 && !bound; scale *= 4) {
        const float* tmp[7] = {0, 0, 0, 0, 0, 0, 0};
        int m = 0;
        for (int i = 0; i < n_in; i++) {
            long long s = (long long)in_sizes[i];
            for (int j = 0; j < 7; j++) {
                if (!tmp[j] && s == want[j] * scale) { tmp[j] = (const float*)d_in[i]; m++; break; }
            }
        }
        if (m == 7) { for (int j = 0; j < 7; j++) ptr[j] = tmp[j]; bound = true; }
    }
    if (!bound && n_in >= 7) {
        for (int j = 0; j < 7; j++) ptr[j] = (const float*)d_in[j];
        bound = true;
    }

    float* outf = (float*)d_out;

    // Output capacity + layout mode — identical to the passing R7/R8 logic.
    long long os = (long long)out_size;
    unsigned capF;
    int mode;
    if (os >= 33554432LL)      { mode = 1; capF = 33554432u; }
    else if (os == 16777216LL) { mode = 0; capF = 16777216u; }
    else {
        mode = 0;
        long long c = os > 0 ? os : 0;
        if (c > 33554432LL) c = 33554432LL;
        capF = (unsigned)c;
    }

    if (!bound || !outf) {
        dummy_kernel<<<1, 32>>>(outf, capF);
        return;
    }

    mlp_kernel<<<BATCH, 64>>>(ptr[0], ptr[1], ptr[2], ptr[3], ptr[4], ptr[5], ptr[6]);

    const int GA = 16 * BATCH;  // 4096 blocks (slab = bits 0..11)
    const int GB = 16 * BATCH;  // 4096 blocks (low = bits 0..11)
    passA_kernel<0, true ><<<GA, 256>>>();
    passB_kernel<0, false, false><<<GB, 256>>>(outf, capF, mode);
    passA_kernel<1, false><<<GA, 256>>>();
    passB_kernel<1, true , false><<<GB, 256>>>(outf, capF, mode);
    passA_kernel<2, false><<<GA, 256>>>();
    passB_kernel<2, true , true ><<<GB, 256>>>(outf, capF, mode);
}

// round 10
// speedup vs baseline: 3.7306x; 1.2101x over previous
#include <cuda_runtime.h>
#include <math.h>

#define NQ 16
#define NS 65536
#define BATCH 256
#define SLIM (BATCH * NS)          /* 16,777,216 floats */
#define MLIM (BATCH * 3 * NQ * 4)  /* 49,152 floats */

__device__ __align__(16) float g_state[SLIM];
__device__ __align__(16) float g_M[MLIM];
__device__ float g_P[48];                       // sigmoid(entangling), 45 used
__device__ __align__(16) float g_F[BATCH * 2048];  // layer-0 low factor (post C0..C9)
__device__ __align__(16) float g_H[BATCH * 64];    // layer-0 high factors H_0,H_1 (post C10..C14)

__device__ __forceinline__ float sigm(float x) { return 1.0f / (1.0f + expf(-x)); }

// In-register 2x2 gate on register-bit kb (N-element tile).
template <int N>
__device__ __forceinline__ void gate_reg(float* v, int kb,
                                         float m00, float m01, float m10, float m11) {
    #pragma unroll
    for (int i = 0; i < N; i++) if (!(i & kb)) {
        const int j = i | kb;
        float a = v[i], c = v[j];
        v[i] = m00 * a + m01 * c;
        v[j] = m10 * a + m11 * c;
    }
}
template <int N>
__device__ __forceinline__ void cnot_reg(float* v, int cb, int tb, float p) {
    const float om = 1.f - p;
    #pragma unroll
    for (int i = 0; i < N; i++) if ((i & cb) && !(i & tb)) {
        const int j = i | tb;
        float a = v[i], c = v[j];
        v[i] = om * a + p * c;
        v[j] = om * c + p * a;
    }
}
template <int N>
__device__ __forceinline__ void cnot_reg_ext(float* v, int tb, bool ctrl, float p) {
    const float pp = ctrl ? p : 0.f;
    const float oo = ctrl ? 1.f - p : 1.f;
    #pragma unroll
    for (int i = 0; i < N; i++) if (!(i & tb)) {
        const int j = i | tb;
        float a = v[i], c = v[j];
        v[i] = oo * a + pp * c;
        v[j] = oo * c + pp * a;
    }
}

__global__ void dummy_kernel(float* outf, unsigned capF) {
    if (capF > 0) outf[0] = 0.f;
}

// ---------------------------------------------------------------------------
// MLP + gate matrices + sigmoid table. One block per batch element.
// ---------------------------------------------------------------------------
__global__ void mlp_kernel(const float* __restrict__ X,
                           const float* __restrict__ rot,
                           const float* __restrict__ ent,
                           const float* __restrict__ W1,
                           const float* __restrict__ b1,
                           const float* __restrict__ W2,
                           const float* __restrict__ b2)
{
    __shared__ float sx[100];
    __shared__ float sa[64];
    __shared__ float sh[16];
    const int b = blockIdx.x;
    const int j = threadIdx.x;  // 64 threads

    if (b == 0 && j < 45) g_P[j] = sigm(ent[j]);

    for (int k = j; k < 100; k += 64) sx[k] = X[b * 100 + k];
    __syncthreads();
    {
        float s = b1[j];
        #pragma unroll 4
        for (int k = 0; k < 100; k++) s = fmaf(sx[k], W1[k * 64 + j], s);
        sa[j] = s > 0.f ? s : 0.f;
    }
    __syncthreads();
    if (j < 16) {
        float s = b2[j];
        #pragma unroll 8
        for (int k = 0; k < 64; k++) s = fmaf(sa[k], W2[k * 16 + j], s);
        sh[j] = tanhf(s);
    }
    __syncthreads();
    if (j < 48) {
        const int l = j >> 4, q = j & 15;
        float hv = 0.5f * sh[q];
        float ax = rot[(l * 16 + q) * 3 + 0] * hv;
        float ay = rot[(l * 16 + q) * 3 + 1] * hv;
        float az = rot[(l * 16 + q) * 3 + 2] * hv;
        float cx, sx2, cy, sy, cz, sz;
        sincosf(ax, &sx2, &cx);
        sincosf(ay, &sy,  &cy);
        sincosf(az, &sz,  &cz);
        float* m = &g_M[((b * 3 + l) * NQ + q) * 4];
        m[0] =  cx * cy * cz;
        m[1] = -sx2 * sy * sz;
        m[2] =  sx2 * sy * cz;
        m[3] =  cx * cy * sz;
    }
}

// ---------------------------------------------------------------------------
// Prep: layer-0 closed form. Post-layer-0 state = F'[l] * H_{bit10(l)}[h],
// l = bits 0..10, h = bits 11..15.
//   F' = (product over qubits 0..10 of M[q][l_q,0]) then CNOT chain C0..C9.
//   H_0 = T * G,  H_1 = T * G_mixed,  where G = product over qubits 11..15,
//   G_mixed = (1-p10) G + p10 G(bit11 flipped),  T = chain C11..C14.
// One block per batch element, 256 threads.
// ---------------------------------------------------------------------------
__global__ void __launch_bounds__(256) prep_kernel()
{
    __shared__ float fA[2048], fB[2048];
    __shared__ float gg[2][32];
    const int b = blockIdx.x;
    const unsigned t = threadIdx.x;
    const float* M = &g_M[b * 3 * 64];  // layer 0 matrices

    // product over qubits 0..10 (thread t = bits 3..10, regs = bits 0..2)
    float ph = 1.f;
    #pragma unroll
    for (int q = 3; q < 11; q++) ph *= M[q * 4 + (((t >> (q - 3)) & 1) ? 2 : 0)];
    #pragma unroll
    for (int r = 0; r < 8; r++) {
        float pr = ph;
        pr *= M[0 + ((r & 1) ? 2 : 0)];
        pr *= M[4 + ((r & 2) ? 2 : 0)];
        pr *= M[8 + ((r & 4) ? 2 : 0)];
        fA[t * 8 + r] = pr;
    }
    __syncthreads();

    // C0..C9 chain on the 2048-vector (ping-pong buffers)
    float* cur = fA;
    float* nxt = fB;
    #pragma unroll
    for (int i = 0; i < 10; i++) {
        const float p = g_P[i], om = 1.f - p;
        const unsigned cb = 1u << i, tb = 1u << (i + 1);
        #pragma unroll
        for (int k = 0; k < 8; k++) {
            const unsigned l = t + 256u * k;
            const float a = cur[l];
            nxt[l] = (l & cb) ? (om * a + p * cur[l ^ tb]) : a;
        }
        __syncthreads();
        float* tmp = cur; cur = nxt; nxt = tmp;
    }
    #pragma unroll
    for (int k = 0; k < 8; k++) {
        const unsigned l = t + 256u * k;
        g_F[b * 2048 + l] = cur[l];
    }

    // High factor: G, then C10 conditioning, then C11..C14 chain on both.
    if (t < 32) {
        float g = 1.f;
        #pragma unroll
        for (int q = 11; q < 16; q++) g *= M[q * 4 + (((t >> (q - 11)) & 1) ? 2 : 0)];
        gg[0][t] = g;
    }
    __syncthreads();
    if (t < 32) {
        const float p = g_P[10];
        gg[1][t] = (1.f - p) * gg[0][t] + p * gg[0][t ^ 1u];
    }
    __syncthreads();
    #pragma unroll
    for (int i = 11; i < 15; i++) {
        const float p = g_P[i], om = 1.f - p;
        const unsigned cb = 1u << (i - 11), tb = 1u << (i - 10);
        float r = 0.f;
        if (t < 64) {
            const unsigned vv = t >> 5, h = t & 31u;
            const float a = gg[vv][h];
            r = (h & cb) ? (om * a + p * gg[vv][h ^ tb]) : a;
        }
        __syncthreads();
        if (t < 64) gg[t >> 5][t & 31u] = r;
        __syncthreads();
    }
    if (t < 64) g_H[b * 64 + t] = gg[t >> 5][t & 31u];
}

// ---------------------------------------------------------------------------
// Pass A: slab of 4096 states (bits 0..11), 256 threads x 16 regs.
// Register phases: m0 = bits 0..3 (thread = bits 4..11),
//                  m1 = bits 4..7, m2 = bits 8..11,
// connected by 2 padded-smem transposes (proven conflict-free, R9).
// MODE 0: load g_state.  MODE 1: generate input from layer-0 factors F',H.
// Ops: m0: [input+G0..3] C0 C1 C2 | m1: [G4..7] C3ext C4 C5 C6
//      m2: [G8..11] C7ext C8 C9 C10, coalesced store.
// ---------------------------------------------------------------------------
#define SMEM_FLOATS 5376
template <int LAYER, int MODE>
__global__ void __launch_bounds__(256) passA_kernel()
{
    __shared__ float sm[SMEM_FLOATS];
    const int hi = blockIdx.x & 15;   // state bits 12..15
    const int b  = blockIdx.x >> 4;
    const unsigned t = threadIdx.x;   // 0..255
    const float* M = &g_M[(b * 3 + LAYER) * 64];
    const float* P = &g_P[LAYER * 15];
    const unsigned base = ((unsigned)b << 16) + ((unsigned)hi << 12);

    float v[16];
    // ---- m0: regs = bits 0..3, thread = bits 4..11 ----
    if (MODE == 1) {
        // post-layer-0 state = F'[l] * H_{bit10}[h]; bit10 = t bit6,
        // h = (hi<<1) | t bit7, l = ((t&127)<<4) | r  (16 consecutive F').
        const float hval = g_H[(unsigned)b * 64u + ((t >> 6) & 1u) * 32u
                               + (((unsigned)hi << 1) | ((t >> 7) & 1u))];
        const float* Fp = &g_F[(unsigned)b * 2048u + ((t & 127u) << 4)];
        #pragma unroll
        for (int k = 0; k < 4; k++) {
            const float4 u = *(const float4*)&Fp[4 * k];
            v[4*k+0] = u.x * hval; v[4*k+1] = u.y * hval;
            v[4*k+2] = u.z * hval; v[4*k+3] = u.w * hval;
        }
    } else {
        #pragma unroll
        for (int k = 0; k < 4; k++) {
            const float4 u = *(const float4*)&g_state[base + (t << 4) + 4u * k];
            v[4*k+0] = u.x; v[4*k+1] = u.y; v[4*k+2] = u.z; v[4*k+3] = u.w;
        }
    }
    gate_reg<16>(v, 1, M[0],  M[1],  M[2],  M[3]);   // G0
    gate_reg<16>(v, 2, M[4],  M[5],  M[6],  M[7]);   // G1
    gate_reg<16>(v, 4, M[8],  M[9],  M[10], M[11]);  // G2
    gate_reg<16>(v, 8, M[12], M[13], M[14], M[15]);  // G3
    cnot_reg<16>(v, 1, 2, P[0]);   // C0 (0->1)
    cnot_reg<16>(v, 2, 4, P[1]);   // C1 (1->2)
    cnot_reg<16>(v, 4, 8, P[2]);   // C2 (2->3)

    // ---- T1: float4 writes, stride-16 reads (padded addressing) ----
    {
        float4* s4 = (float4*)sm;
        const unsigned w4 = t * 5u + 4u * (t >> 4);
        #pragma unroll
        for (int k = 0; k < 4; k++)
            s4[w4 + k] = make_float4(v[4*k], v[4*k+1], v[4*k+2], v[4*k+3]);
    }
    __syncthreads();
    {
        const unsigned rbase = (t & 15u) + 336u * (t >> 4);
        #pragma unroll
        for (int r = 0; r < 16; r++) v[r] = sm[rbase + 20u * r];
    }
    // ---- m1: regs = bits 4..7 ----
    gate_reg<16>(v, 1, M[16], M[17], M[18], M[19]);  // G4
    gate_reg<16>(v, 2, M[20], M[21], M[22], M[23]);  // G5
    gate_reg<16>(v, 4, M[24], M[25], M[26], M[27]);  // G6
    gate_reg<16>(v, 8, M[28], M[29], M[30], M[31]);  // G7
    cnot_reg_ext<16>(v, 1, (t & 8u) != 0, P[3]);  // C3 (ctrl bit3, tgt bit4)
    cnot_reg<16>(v, 1, 2, P[4]);                  // C4 (4->5)
    cnot_reg<16>(v, 2, 4, P[5]);                  // C5 (5->6)
    cnot_reg<16>(v, 4, 8, P[6]);                  // C6 (6->7)

    __syncthreads();  // WAR before buffer reuse

    // ---- T2: stride-16 writes, stride-272 reads ----
    {
        const unsigned wbase = (t & 15u) + 272u * (t >> 4);
        #pragma unroll
        for (int r = 0; r < 16; r++) sm[wbase + 16u * r] = v[r];
    }
    __syncthreads();
    {
        #pragma unroll
        for (int r = 0; r < 16; r++) v[r] = sm[272u * r + t];
    }
    // ---- m2: regs = bits 8..11, thread = bits 0..7 ----
    gate_reg<16>(v, 1, M[32], M[33], M[34], M[35]);  // G8
    gate_reg<16>(v, 2, M[36], M[37], M[38], M[39]);  // G9
    gate_reg<16>(v, 4, M[40], M[41], M[42], M[43]);  // G10
    gate_reg<16>(v, 8, M[44], M[45], M[46], M[47]);  // G11
    cnot_reg_ext<16>(v, 1, (t & 128u) != 0, P[7]);  // C7 (ctrl bit7, tgt bit8)
    cnot_reg<16>(v, 1, 2, P[8]);                    // C8 (8->9)
    cnot_reg<16>(v, 2, 4, P[9]);                    // C9 (9->10)
    cnot_reg<16>(v, 4, 8, P[10]);                   // C10 (10->11)

    #pragma unroll
    for (int r = 0; r < 16; r++) g_state[base + ((unsigned)r << 8) + t] = v[r];
}

// ---------------------------------------------------------------------------
// Pass B: each thread owns the 16 states spanning bits 12..15 for one fixed
// low index (bits 0..11). Gates G12..15, C11 (uniform ctrl bit 11), C12..C14.
// OUT: final output write per mode (0 = flat floats, 1 = (re,0)).
// ---------------------------------------------------------------------------
template <int LAYER, bool OUT>
__global__ void __launch_bounds__(256) passB_kernel(float* __restrict__ outf,
                                                    unsigned capF, int mode)
{
    const int lowblk = blockIdx.x & 15;  // low bits 8..11
    const int b = blockIdx.x >> 4;
    const unsigned t = threadIdx.x;
    const unsigned low = ((unsigned)lowblk << 8) | t;
    const float* M = &g_M[(b * 3 + LAYER) * 64];
    const float* P = &g_P[LAYER * 15];
    const unsigned base = ((unsigned)b << 16) + low;

    float w[16];
    #pragma unroll
    for (int k = 0; k < 16; k++) w[k] = g_state[base + ((unsigned)k << 12)];

    gate_reg<16>(w, 1, M[48], M[49], M[50], M[51]);  // G12
    gate_reg<16>(w, 2, M[52], M[53], M[54], M[55]);  // G13
    gate_reg<16>(w, 4, M[56], M[57], M[58], M[59]);  // G14
    gate_reg<16>(w, 8, M[60], M[61], M[62], M[63]);  // G15
    cnot_reg_ext<16>(w, 1, (low & 2048u) != 0, P[11]);  // C11 (ctrl bit11, tgt bit12)
    cnot_reg<16>(w, 1, 2, P[12]);                       // C12 (12->13)
    cnot_reg<16>(w, 2, 4, P[13]);                       // C13 (13->14)
    cnot_reg<16>(w, 4, 8, P[14]);                       // C14 (14->15)

    if (OUT) {
        if (mode == 1) {
            #pragma unroll
            for (int k = 0; k < 16; k++) {
                unsigned idx = base + ((unsigned)k << 12);
                unsigned p2 = 2u * idx;
                if (p2 + 1u < capF) *(float2*)&outf[p2] = make_float2(w[k], 0.f);
            }
        } else {
            #pragma unroll
            for (int k = 0; k < 16; k++) {
                unsigned idx = base + ((unsigned)k << 12);
                if (idx < capF) outf[idx] = w[k];
            }
        }
    } else {
        #pragma unroll
        for (int k = 0; k < 16; k++) g_state[base + ((unsigned)k << 12)] = w[k];
    }
}

// ---------------------------------------------------------------------------
extern "C" void kernel_launch(void* const* d_in, const int* in_sizes, int n_in,
                              void* d_out, int out_size)
{
    static const long long want[7] = {25600, 144, 45, 6400, 64, 1024, 16};
    const float* ptr[7] = {0, 0, 0, 0, 0, 0, 0};

    bool bound = false;
    for (int scale = 1; scale <= 4 && !bound; scale *= 4) {
        const float* tmp[7] = {0, 0, 0, 0, 0, 0, 0};
        int m = 0;
        for (int i = 0; i < n_in; i++) {
            long long s = (long long)in_sizes[i];
            for (int j = 0; j < 7; j++) {
                if (!tmp[j] && s == want[j] * scale) { tmp[j] = (const float*)d_in[i]; m++; break; }
            }
        }
        if (m == 7) { for (int j = 0; j < 7; j++) ptr[j] = tmp[j]; bound = true; }
    }
    if (!bound && n_in >= 7) {
        for (int j = 0; j < 7; j++) ptr[j] = (const float*)d_in[j];
        bound = true;
    }

    float* outf = (float*)d_out;

    // Output capacity + layout mode — identical to the passing R7-R9 logic.
    long long os = (long long)out_size;
    unsigned capF;
    int mode;
    if (os >= 33554432LL)      { mode = 1; capF = 33554432u; }
    else if (os == 16777216LL) { mode = 0; capF = 16777216u; }
    else {
        mode = 0;
        long long c = os > 0 ? os : 0;
        if (c > 33554432LL) c = 33554432LL;
        capF = (unsigned)c;
    }

    if (!bound || !outf) {
        dummy_kernel<<<1, 32>>>(outf, capF);
        return;
    }

    mlp_kernel<<<BATCH, 64>>>(ptr[0], ptr[1], ptr[2], ptr[3], ptr[4], ptr[5], ptr[6]);
    prep_kernel<<<BATCH, 256>>>();   // layer-0 closed form: F', H

    const int GA = 16 * BATCH;  // 4096 blocks
    // Layer 1: input generated from layer-0 factors (no state read)
    passA_kernel<1, 1><<<GA, 256>>>();
    passB_kernel<1, false><<<GA, 256>>>(outf, capF, mode);
    // Layer 2
    passA_kernel<2, 0><<<GA, 256>>>();
    passB_kernel<2, true ><<<GA, 256>>>(outf, capF, mode);
}